// round 2
// baseline (speedup 1.0000x reference)
#include <cuda_runtime.h>
#include <cstdint>

#define TT 32
#define NN 20000
#define FF 128
#define HH 128
#define CC 10

// Scratch: U[t][n][o] = X[t,n,:]@W_ih^T + b_ih + b_hh   (327.68 MB)
__device__ float g_U[(size_t)TT * NN * HH];

__device__ __forceinline__ void fma4(float4& a, float s, float4 w) {
    a.x = fmaf(s, w.x, a.x);
    a.y = fmaf(s, w.y, a.y);
    a.z = fmaf(s, w.z, a.z);
    a.w = fmaf(s, w.w, a.w);
}

// ---------------------------------------------------------------------------
// Kernel 1: U = X @ W_ih^T + (b_ih + b_hh).  M = T*N = 640000 rows, K=F=128,
// out = H=128.  Tile: 128 rows/CTA, 256 threads = 8 warps x 16 rows, lane owns
// 4 output cols.  W_ih^T resident in SMEM; X streamed in 32-wide k chunks.
// ---------------------------------------------------------------------------
__global__ __launch_bounds__(256, 2) void u_gemm_kernel(
    const float* __restrict__ X,
    const float* __restrict__ W_ih,
    const float* __restrict__ b_ih,
    const float* __restrict__ b_hh)
{
    extern __shared__ float sm1[];
    float* Wsh = sm1;            // [128][128]  Wsh[f][o] = W_ih[o][f]
    float* xs  = sm1 + 16384;    // [128][32]   x chunk

    const int tid = threadIdx.x;
    const int warp = tid >> 5;
    const int lane = tid & 31;

    for (int i = tid; i < 16384; i += 256) {
        int f = i >> 7, o = i & 127;
        Wsh[i] = W_ih[o * 128 + f];
    }

    float4 bias;
    {
        float4 a = ((const float4*)b_ih)[lane];
        float4 b = ((const float4*)b_hh)[lane];
        bias = make_float4(a.x + b.x, a.y + b.y, a.z + b.z, a.w + b.w);
    }

    float4 acc[16];
#pragma unroll
    for (int i = 0; i < 16; i++) acc[i] = bias;

    const size_t row0 = (size_t)blockIdx.x * 128;
    const float4* Xg  = (const float4*)X;
    float4* xs4 = (float4*)xs;
    const float4* W4  = (const float4*)Wsh;

    for (int kc = 0; kc < 128; kc += 32) {
        __syncthreads();  // xs free (also orders Wsh before first compute)
#pragma unroll
        for (int j = 0; j < 4; j++) {
            int fi = tid + j * 256;       // 0..1023 float4 slots
            int r = fi >> 3, c = fi & 7;  // 8 float4 per row-chunk
            xs4[r * 8 + c] = Xg[(row0 + r) * 32 + (kc >> 2) + c];
        }
        __syncthreads();
#pragma unroll 2
        for (int k = 0; k < 32; k += 4) {
            float4 w0 = W4[(kc + k + 0) * 32 + lane];
            float4 w1 = W4[(kc + k + 1) * 32 + lane];
            float4 w2 = W4[(kc + k + 2) * 32 + lane];
            float4 w3 = W4[(kc + k + 3) * 32 + lane];
#pragma unroll
            for (int i = 0; i < 16; i++) {
                float4 hv = xs4[(warp * 16 + i) * 8 + (k >> 2)];
                fma4(acc[i], hv.x, w0);
                fma4(acc[i], hv.y, w1);
                fma4(acc[i], hv.z, w2);
                fma4(acc[i], hv.w, w3);
            }
        }
    }

    float4* Ug = (float4*)g_U;
#pragma unroll
    for (int i = 0; i < 16; i++)
        Ug[(row0 + warp * 16 + i) * 32 + lane] = acc[i];
}

// ---------------------------------------------------------------------------
// Kernel 2: fused recurrence + LayerNorm + online-softmax attention + dense.
// grid = 148 CTAs (one wave), 136 rows/CTA = 8 warps x 17 rows; lane owns 4
// output channels.  h and G live in SMEM; m/s per-row in registers.
//   per step: acc = U[t] (global) ; acc += h @ W_hh^T ; relu ; h := acc ;
//             LN(acc) -> o ; logit l = o.attn_W + b ; online softmax update of
//             (m, s, G += w*o).  Final: out = dense_b + W_d @ (G/s).
// ---------------------------------------------------------------------------
__global__ __launch_bounds__(256, 1) void rnn_fused_kernel(
    const float* __restrict__ W_hh,
    const float* __restrict__ ln_g,  const float* __restrict__ ln_b,
    const float* __restrict__ attn_W, const float* __restrict__ attn_b,
    const float* __restrict__ dense_W, const float* __restrict__ dense_b,
    float* __restrict__ out)
{
    extern __shared__ float sm2[];
    float* Whh_s = sm2;                 // [128][128]  Whh_s[j][o] = W_hh[o][j]
    float* h_s   = sm2 + 16384;         // [136][128]
    float* G_s   = h_s + 136 * 128;     // [136][128]
    float* Wd_s  = G_s + 136 * 128;     // [10][128]
    float* db_s  = Wd_s + 1280;         // [10]

    const int tid = threadIdx.x;
    const int warp = tid >> 5;
    const int lane = tid & 31;

    for (int i = tid; i < 16384; i += 256) {
        int j = i >> 7, o = i & 127;
        Whh_s[i] = W_hh[o * 128 + j];
    }
    for (int i = tid; i < 1280; i += 256) Wd_s[i] = dense_W[i];
    if (tid < CC) db_s[tid] = dense_b[tid];

    const float4 g4  = ((const float4*)ln_g)[lane];
    const float4 be4 = ((const float4*)ln_b)[lane];
    const float4 aw4 = ((const float4*)attn_W)[lane];
    const float ab = attn_b[0];

    const int wbase = warp * 17;                 // local row base
    const int n0 = blockIdx.x * 136 + wbase;     // global row base

    float4* h4 = (float4*)h_s;
    float4* G4 = (float4*)G_s;
    const float4* W4 = (const float4*)Whh_s;
    const float4* U4 = (const float4*)g_U;

    const float4 z4 = make_float4(0.f, 0.f, 0.f, 0.f);

    // h := U[0]  (initial hidden, no relu), G := 0
#pragma unroll
    for (int i = 0; i < 17; i++) {
        int n = n0 + i;
        float4 v = z4;
        if (n < NN) v = U4[(size_t)n * 32 + lane];
        h4[(wbase + i) * 32 + lane] = v;
        G4[(wbase + i) * 32 + lane] = z4;
    }
    float mrow[17], srow[17];
#pragma unroll
    for (int i = 0; i < 17; i++) { mrow[i] = -INFINITY; srow[i] = 0.f; }
    __syncthreads();

    for (int t = 0; t < TT; t++) {
        float4 acc[17];
        const float4* Ut = U4 + (size_t)t * NN * 32;
#pragma unroll
        for (int i = 0; i < 17; i++) {
            int n = n0 + i;
            acc[i] = (n < NN) ? Ut[(size_t)n * 32 + lane] : z4;
        }
        // acc += h @ W_hh^T
#pragma unroll 2
        for (int k = 0; k < 128; k += 4) {
            float4 w0 = W4[(k + 0) * 32 + lane];
            float4 w1 = W4[(k + 1) * 32 + lane];
            float4 w2 = W4[(k + 2) * 32 + lane];
            float4 w3 = W4[(k + 3) * 32 + lane];
#pragma unroll
            for (int i = 0; i < 17; i++) {
                float4 hv = h4[(wbase + i) * 32 + (k >> 2)];
                fma4(acc[i], hv.x, w0);
                fma4(acc[i], hv.y, w1);
                fma4(acc[i], hv.z, w2);
                fma4(acc[i], hv.w, w3);
            }
        }
        // relu
#pragma unroll
        for (int i = 0; i < 17; i++) {
            acc[i].x = fmaxf(acc[i].x, 0.f);
            acc[i].y = fmaxf(acc[i].y, 0.f);
            acc[i].z = fmaxf(acc[i].z, 0.f);
            acc[i].w = fmaxf(acc[i].w, 0.f);
        }
        __syncthreads();  // everyone done reading old h
#pragma unroll
        for (int i = 0; i < 17; i++)
            h4[(wbase + i) * 32 + lane] = acc[i];

        // LayerNorm + attention logit + online softmax accumulation
#pragma unroll 1
        for (int i = 0; i < 17; i++) {
            float4 y = acc[i];
            float s1 = y.x + y.y + y.z + y.w;
            float s2 = fmaf(y.x, y.x, fmaf(y.y, y.y, fmaf(y.z, y.z, y.w * y.w)));
#pragma unroll
            for (int off = 16; off > 0; off >>= 1) {
                s1 += __shfl_xor_sync(0xffffffffu, s1, off);
                s2 += __shfl_xor_sync(0xffffffffu, s2, off);
            }
            float mean = s1 * (1.0f / 128.0f);
            float var  = fmaf(s2, 1.0f / 128.0f, -mean * mean);
            float rstd = rsqrtf(var + 1e-5f);
            float4 o;
            o.x = fmaf((y.x - mean) * rstd, g4.x, be4.x);
            o.y = fmaf((y.y - mean) * rstd, g4.y, be4.y);
            o.z = fmaf((y.z - mean) * rstd, g4.z, be4.z);
            o.w = fmaf((y.w - mean) * rstd, g4.w, be4.w);
            float lp = fmaf(o.x, aw4.x, fmaf(o.y, aw4.y, fmaf(o.z, aw4.z, o.w * aw4.w)));
#pragma unroll
            for (int off = 16; off > 0; off >>= 1)
                lp += __shfl_xor_sync(0xffffffffu, lp, off);
            float l = lp + ab;

            float mo = mrow[i];
            float mn = fmaxf(mo, l);
            float alpha = __expf(mo - mn);   // exp(-inf) = 0 on first step
            float beta  = __expf(l - mn);
            srow[i] = fmaf(srow[i], alpha, beta);
            mrow[i] = mn;

            int gi = (wbase + i) * 32 + lane;
            float4 g = G4[gi];
            g.x = fmaf(g.x, alpha, beta * o.x);
            g.y = fmaf(g.y, alpha, beta * o.y);
            g.z = fmaf(g.z, alpha, beta * o.z);
            g.w = fmaf(g.w, alpha, beta * o.w);
            G4[gi] = g;
        }
        __syncthreads();  // h visible before next step's GEMM
    }

    // out[n, c] = dense_b[c] + (W_d[c,:] . G[n,:]) / s[n]
#pragma unroll 1
    for (int i = 0; i < 17; i++) {
        int n = n0 + i;
        if (n >= NN) continue;
        float inv = 1.0f / srow[i];
        float4 g = G4[(wbase + i) * 32 + lane];
#pragma unroll
        for (int c = 0; c < CC; c++) {
            float4 wd = ((const float4*)Wd_s)[c * 32 + lane];
            float p = fmaf(g.x, wd.x, fmaf(g.y, wd.y, fmaf(g.z, wd.z, g.w * wd.w)));
#pragma unroll
            for (int off = 16; off > 0; off >>= 1)
                p += __shfl_xor_sync(0xffffffffu, p, off);
            if (lane == 0) out[n * CC + c] = fmaf(p, inv, db_s[c]);
        }
    }
}

// ---------------------------------------------------------------------------
extern "C" void kernel_launch(void* const* d_in, const int* in_sizes, int n_in,
                              void* d_out, int out_size)
{
    const float* X       = (const float*)d_in[0];
    const float* W_ih    = (const float*)d_in[1];
    const float* W_hh    = (const float*)d_in[2];
    const float* b_ih    = (const float*)d_in[3];
    const float* b_hh    = (const float*)d_in[4];
    const float* ln_g    = (const float*)d_in[5];
    const float* ln_b    = (const float*)d_in[6];
    const float* attn_W  = (const float*)d_in[7];
    const float* attn_b  = (const float*)d_in[8];
    const float* dense_W = (const float*)d_in[9];
    const float* dense_b = (const float*)d_in[10];
    float* out = (float*)d_out;

    const int smem1 = (16384 + 128 * 32) * 4;                      // 81920 B
    const int smem2 = (16384 + 136 * 128 * 2 + 1280 + 16) * 4;     // ~210 KB

    cudaFuncSetAttribute(u_gemm_kernel,
                         cudaFuncAttributeMaxDynamicSharedMemorySize, smem1);
    cudaFuncSetAttribute(rnn_fused_kernel,
                         cudaFuncAttributeMaxDynamicSharedMemorySize, smem2);

    // Phase 1: U = X@W_ih^T + b_ih + b_hh   (640000 x 128, K=128)
    u_gemm_kernel<<<(TT * NN) / 128, 256, smem1>>>(X, W_ih, b_ih, b_hh);

    // Phase 2: fused recurrence + LN + attention-softmax + dense head
    rnn_fused_kernel<<<148, 256, smem2>>>(W_hh, ln_g, ln_b, attn_W, attn_b,
                                          dense_W, dense_b, out);
}

// round 4
// speedup vs baseline: 4.2004x; 4.2004x over previous
#include <cuda_runtime.h>
#include <cuda_bf16.h>
#include <cstdint>

#define TT 32
#define NN 20000
#define CC 10

// Scratch: U[t][n][o] = X[t,n,:]@W_ih^T + b_ih + b_hh  (fp32, 327.68 MB)
__device__ float g_U[(size_t)TT * NN * 128];

// ---------------------------------------------------------------------------
// helpers (plain sm_100-legal: mma.sync bf16, ldmatrix, cp.async)
// ---------------------------------------------------------------------------
__device__ __forceinline__ uint32_t smem_u32_of(const void* p) {
    uint32_t a;
    asm("{ .reg .u64 t; cvta.to.shared.u64 t, %1; cvt.u32.u64 %0, t; }" : "=r"(a) : "l"(p));
    return a;
}
__device__ __forceinline__ void mma_bf16(float* c, const uint32_t* a, const uint32_t* b) {
    asm volatile("mma.sync.aligned.m16n8k16.row.col.f32.bf16.bf16.f32 "
        "{%0,%1,%2,%3}, {%4,%5,%6,%7}, {%8,%9}, {%0,%1,%2,%3};"
        : "+f"(c[0]), "+f"(c[1]), "+f"(c[2]), "+f"(c[3])
        : "r"(a[0]), "r"(a[1]), "r"(a[2]), "r"(a[3]), "r"(b[0]), "r"(b[1]));
}
__device__ __forceinline__ void ldsm4(uint32_t* r, uint32_t addr) {
    asm volatile("ldmatrix.sync.aligned.m8n8.x4.shared.b16 {%0,%1,%2,%3}, [%4];"
        : "=r"(r[0]), "=r"(r[1]), "=r"(r[2]), "=r"(r[3]) : "r"(addr));
}
__device__ __forceinline__ void ldsm2(uint32_t* r, uint32_t addr) {
    asm volatile("ldmatrix.sync.aligned.m8n8.x2.shared.b16 {%0,%1}, [%2];"
        : "=r"(r[0]), "=r"(r[1]) : "r"(addr));
}
#define CP16(dst, src) asm volatile("cp.async.cg.shared.global [%0], [%1], 16;" :: "r"(dst), "l"(src))
#define CP_COMMIT()    asm volatile("cp.async.commit_group;" ::: "memory")
#define CP_WAIT0()     asm volatile("cp.async.wait_group 0;" ::: "memory")

// swizzled byte offset in a [rows][128] bf16 tile (256 B/row, 16 chunks of 16B;
// chunk index XORed with row&7 -> conflict-free ldmatrix & STS)
__device__ __forceinline__ uint32_t hswz(int r, int k) {
    int k8 = k >> 3;
    int s = (k8 & 8) | ((k8 ^ r) & 7);
    return (uint32_t)(r * 256 + s * 16 + (k & 7) * 2);
}
// pack two fp32 -> bf16x2 (low=a, high=b)
__device__ __forceinline__ uint32_t packbf(float a, float b) {
    uint32_t p;
    asm("cvt.rn.bf16x2.f32 %0, %1, %2;" : "=r"(p) : "f"(b), "f"(a));
    return p;
}
// convert fp32 weight [128][128] -> split-bf16 hi/lo swizzled SMEM tiles
__device__ __forceinline__ void conv_weight(const float* __restrict__ W,
                                            char* hi, char* lo, int tid) {
    for (int idx = tid; idx < 16384; idx += 256) {
        int r = idx >> 7, k = idx & 127;
        float w = W[idx];
        __nv_bfloat16 wh = __float2bfloat16(w);
        uint32_t o = hswz(r, k);
        *(__nv_bfloat16*)(hi + o) = wh;
        *(__nv_bfloat16*)(lo + o) = __float2bfloat16(w - __bfloat162float(wh));
    }
}

// ===========================================================================
// Kernel 1: U = X @ W_ih^T + (b_ih + b_hh).  256 rows/CTA, grid 2500.
// 8 warps, warp w owns output cols [16w,16w+16). split-bf16, 3 mma products.
// ===========================================================================
#define K1_WIH_HI 0
#define K1_WIH_LO 32768
#define K1_X_HI   65536
#define K1_X_LO   131072
#define K1_STAGE  65536      /* overlays X after mma */
#define K1_BIAS   196608
#define K1_SMEM   197120

__global__ __launch_bounds__(256, 1) void u_gemm(
    const float* __restrict__ X,
    const float* __restrict__ W_ih,
    const float* __restrict__ b_ih,
    const float* __restrict__ b_hh)
{
    extern __shared__ char sm[];
    const uint32_t sb = smem_u32_of(sm);
    const int tid = threadIdx.x, warp = tid >> 5, lane = tid & 31;
    const int g = lane >> 2, q4 = lane & 3;
    const int nw = warp * 16;
    const size_t row0 = (size_t)blockIdx.x * 256;

    conv_weight(W_ih, sm + K1_WIH_HI, sm + K1_WIH_LO, tid);
    if (tid < 128) ((float*)(sm + K1_BIAS))[tid] = b_ih[tid] + b_hh[tid];

    // load + convert X tile [256][128] fp32 -> bf16 hi/lo swizzled
    {
        const float4* X4 = (const float4*)X;
#pragma unroll
        for (int j = 0; j < 32; j++) {
            int fi = tid + j * 256;           // 0..8191
            int r = fi >> 5, c4 = fi & 31;
            float4 x = X4[(row0 + r) * 32 + c4];
            int k = c4 * 4;
            uint32_t h0 = packbf(x.x, x.y), h1 = packbf(x.z, x.w);
            float r0 = x.x - __uint_as_float(h0 << 16);
            float r1 = x.y - __uint_as_float(h0 & 0xffff0000u);
            float r2 = x.z - __uint_as_float(h1 << 16);
            float r3 = x.w - __uint_as_float(h1 & 0xffff0000u);
            uint32_t l0 = packbf(r0, r1), l1 = packbf(r2, r3);
            *(uint2*)(sm + K1_X_HI + hswz(r, k)) = make_uint2(h0, h1);
            *(uint2*)(sm + K1_X_LO + hswz(r, k)) = make_uint2(l0, l1);
        }
    }
    __syncthreads();

    float acc[16][2][4];
#pragma unroll
    for (int mt = 0; mt < 16; mt++)
#pragma unroll
        for (int nt = 0; nt < 2; nt++)
#pragma unroll
            for (int i = 0; i < 4; i++) acc[mt][nt][i] = 0.f;

#pragma unroll 1
    for (int k0 = 0; k0 < 128; k0 += 16) {
        uint32_t bh0[2], bh1[2], bl0[2], bl1[2];
        {
            int bn = nw + (lane & 7);
            int bk = k0 + (((lane >> 3) & 1) << 3);
            ldsm2(bh0, sb + K1_WIH_HI + hswz(bn, bk));
            ldsm2(bh1, sb + K1_WIH_HI + hswz(bn + 8, bk));
            ldsm2(bl0, sb + K1_WIH_LO + hswz(bn, bk));
            ldsm2(bl1, sb + K1_WIH_LO + hswz(bn + 8, bk));
        }
        const int ar = lane & 15, akb = ((lane >> 4) << 3) + k0;
#pragma unroll
        for (int mt = 0; mt < 16; mt++) {
            uint32_t ah[4], al[4];
            ldsm4(ah, sb + K1_X_HI + hswz(mt * 16 + ar, akb));
            ldsm4(al, sb + K1_X_LO + hswz(mt * 16 + ar, akb));
            mma_bf16(acc[mt][0], ah, bh0);
            mma_bf16(acc[mt][1], ah, bh1);
            mma_bf16(acc[mt][0], ah, bl0);
            mma_bf16(acc[mt][1], ah, bl1);
            mma_bf16(acc[mt][0], al, bh0);
            mma_bf16(acc[mt][1], al, bh1);
        }
    }
    __syncthreads();   // X tiles no longer needed -> stage region free

    // +bias, stage to SMEM fp32, coalesced STG
    const int cA = nw + q4 * 2;
    float b4[4];
    b4[0] = ((float*)(sm + K1_BIAS))[cA];
    b4[1] = ((float*)(sm + K1_BIAS))[cA + 1];
    b4[2] = ((float*)(sm + K1_BIAS))[cA + 8];
    b4[3] = ((float*)(sm + K1_BIAS))[cA + 9];
#pragma unroll
    for (int mt = 0; mt < 16; mt++)
#pragma unroll
        for (int rh = 0; rh < 2; rh++) {
            int r = mt * 16 + g + rh * 8;
            *(float2*)(sm + K1_STAGE + r * 512 + cA * 4) =
                make_float2(acc[mt][0][rh * 2] + b4[0], acc[mt][0][rh * 2 + 1] + b4[1]);
            *(float2*)(sm + K1_STAGE + r * 512 + (cA + 8) * 4) =
                make_float2(acc[mt][1][rh * 2] + b4[2], acc[mt][1][rh * 2 + 1] + b4[3]);
        }
    __syncthreads();
    {
        float4* U4 = (float4*)g_U;
#pragma unroll
        for (int j = 0; j < 32; j++) {
            int fi = tid + j * 256;
            int r = fi >> 5, c4 = fi & 31;
            U4[(row0 + r) * 32 + c4] = *(float4*)(sm + K1_STAGE + fi * 16);
        }
    }
}

// ===========================================================================
// Kernel 2: fused recurrence + LN + online-softmax attention + dense head.
// 144 rows/CTA, grid 139 (one wave). 8 warps n-split (16 cols each).
// ===========================================================================
#define WHH_HI 0
#define WHH_LO 32768
#define H_HI   65536
#define H_LO   102400
#define UBUF   139264          /* [144][128] fp32 (73728 B); final: OUTS overlay */
#define RED_O  212992          /* float2 [8][144] */
#define LP_O   222208          /* float  [8][144] */
#define RAB_O  226816          /* float2 [144] (also init temp) */
#define AWG_O  227968          /* float [128] = attn_W*gamma */
#define SCAL_O 228480          /* float[2]: S1, S2 */
#define WGS_O  228544          /* float[10] */
#define WB_O   228584          /* float[10] */
#define K2_SMEM 228640

__global__ __launch_bounds__(256, 1) void rnn_fused(
    const float* __restrict__ W_hh,
    const float* __restrict__ ln_g,  const float* __restrict__ ln_b,
    const float* __restrict__ attn_W, const float* __restrict__ attn_b,
    const float* __restrict__ dense_W, const float* __restrict__ dense_b,
    float* __restrict__ out)
{
    extern __shared__ char sm[];
    const uint32_t sb = smem_u32_of(sm);
    const int tid = threadIdx.x, warp = tid >> 5, lane = tid & 31;
    const int g = lane >> 2, q4 = lane & 3;
    const int nw = warp * 16;
    const int n0 = blockIdx.x * 144;
    const int cA = nw + q4 * 2;

    // prefetch U[0]
    auto prefetchU = [&](int t) {
#pragma unroll
        for (int j = 0; j < 18; j++) {
            int fi = tid + j * 256;                 // 0..4607 16B chunks
            int lr = fi >> 5, c4 = fi & 31;
            int gr = n0 + lr; if (gr > NN - 1) gr = NN - 1;
            const float* src = g_U + ((size_t)t * NN + gr) * 128 + c4 * 4;
            CP16(sb + UBUF + fi * 16, src);
        }
        CP_COMMIT();
    };
    prefetchU(0);

    conv_weight(W_hh, sm + WHH_HI, sm + WHH_LO, tid);
    if (tid < 128) {
        float aw = attn_W[tid], gg = ln_g[tid];
        ((float*)(sm + AWG_O))[tid] = aw * gg;
        ((float*)(sm + RAB_O))[tid] = aw * gg;            // temp for S1
        ((float*)(sm + RAB_O + 512))[tid] = aw * ln_b[tid]; // temp for S2
    }
    __syncthreads();
    if (tid == 0) {
        float s1 = 0.f, s2 = 0.f;
        for (int c = 0; c < 128; c++) {
            s1 += ((float*)(sm + RAB_O))[c];
            s2 += ((float*)(sm + RAB_O + 512))[c];
        }
        ((float*)(sm + SCAL_O))[0] = s1;
        ((float*)(sm + SCAL_O))[1] = s2 + attn_b[0];
    }
    CP_WAIT0();
    __syncthreads();

    const float S1 = ((float*)(sm + SCAL_O))[0];
    const float S2 = ((float*)(sm + SCAL_O))[1];
    float awg4[4];
    awg4[0] = ((float*)(sm + AWG_O))[cA];
    awg4[1] = ((float*)(sm + AWG_O))[cA + 1];
    awg4[2] = ((float*)(sm + AWG_O))[cA + 8];
    awg4[3] = ((float*)(sm + AWG_O))[cA + 9];

    // h0 = U[0]  (no relu): pack to h SMEM
#pragma unroll
    for (int mt = 0; mt < 9; mt++)
#pragma unroll
        for (int rh = 0; rh < 2; rh++) {
            int r = mt * 16 + g + rh * 8;
            float2 u0 = *(float2*)(sm + UBUF + r * 512 + cA * 4);
            float2 u1 = *(float2*)(sm + UBUF + r * 512 + (cA + 8) * 4);
            uint32_t p0 = packbf(u0.x, u0.y), p1 = packbf(u1.x, u1.y);
            *(uint32_t*)(sm + H_HI + hswz(r, cA)) = p0;
            *(uint32_t*)(sm + H_HI + hswz(r, cA + 8)) = p1;
            uint32_t l0 = packbf(u0.x - __uint_as_float(p0 << 16),
                                 u0.y - __uint_as_float(p0 & 0xffff0000u));
            uint32_t l1 = packbf(u1.x - __uint_as_float(p1 << 16),
                                 u1.y - __uint_as_float(p1 & 0xffff0000u));
            *(uint32_t*)(sm + H_LO + hswz(r, cA)) = l0;
            *(uint32_t*)(sm + H_LO + hswz(r, cA + 8)) = l1;
        }
    __syncthreads();

    float P[9][2][4];
#pragma unroll
    for (int mt = 0; mt < 9; mt++)
#pragma unroll
        for (int nt = 0; nt < 2; nt++)
#pragma unroll
            for (int i = 0; i < 4; i++) P[mt][nt][i] = 0.f;
    float rs_m = -INFINITY, rs_s = 0.f, rs_q = 0.f;   // row state (tid<144)

    float acc[9][2][4];
    for (int t = 0; t < TT; t++) {
#pragma unroll
        for (int mt = 0; mt < 9; mt++)
#pragma unroll
            for (int nt = 0; nt < 2; nt++)
#pragma unroll
                for (int i = 0; i < 4; i++) acc[mt][nt][i] = 0.f;

        // ---- mma: acc = h @ W_hh^T  (3 split-bf16 products) ----
#pragma unroll 1
        for (int k0 = 0; k0 < 128; k0 += 16) {
            uint32_t bh0[2], bh1[2], bl0[2], bl1[2];
            {
                int bn = nw + (lane & 7);
                int bk = k0 + (((lane >> 3) & 1) << 3);
                ldsm2(bh0, sb + WHH_HI + hswz(bn, bk));
                ldsm2(bh1, sb + WHH_HI + hswz(bn + 8, bk));
                ldsm2(bl0, sb + WHH_LO + hswz(bn, bk));
                ldsm2(bl1, sb + WHH_LO + hswz(bn + 8, bk));
            }
            const int ar = lane & 15, akb = ((lane >> 4) << 3) + k0;
#pragma unroll
            for (int mt = 0; mt < 9; mt++) {
                uint32_t ah[4], al[4];
                ldsm4(ah, sb + H_HI + hswz(mt * 16 + ar, akb));
                ldsm4(al, sb + H_LO + hswz(mt * 16 + ar, akb));
                mma_bf16(acc[mt][0], ah, bh0);
                mma_bf16(acc[mt][1], ah, bh1);
                mma_bf16(acc[mt][0], ah, bl0);
                mma_bf16(acc[mt][1], ah, bl1);
                mma_bf16(acc[mt][0], al, bh0);
                mma_bf16(acc[mt][1], al, bh1);
            }
        }

        CP_WAIT0();           // U[t] landed
        __syncthreads();      // everyone done with mma reads of h + U present

        // h = relu(acc + U)
#pragma unroll
        for (int mt = 0; mt < 9; mt++)
#pragma unroll
            for (int rh = 0; rh < 2; rh++) {
                int r = mt * 16 + g + rh * 8;
                float2 u0 = *(float2*)(sm + UBUF + r * 512 + cA * 4);
                float2 u1 = *(float2*)(sm + UBUF + r * 512 + (cA + 8) * 4);
                acc[mt][0][rh * 2]     = fmaxf(acc[mt][0][rh * 2]     + u0.x, 0.f);
                acc[mt][0][rh * 2 + 1] = fmaxf(acc[mt][0][rh * 2 + 1] + u0.y, 0.f);
                acc[mt][1][rh * 2]     = fmaxf(acc[mt][1][rh * 2]     + u1.x, 0.f);
                acc[mt][1][rh * 2 + 1] = fmaxf(acc[mt][1][rh * 2 + 1] + u1.y, 0.f);
            }
        __syncthreads();      // Ubuf consumed
        if (t < TT - 1) prefetchU(t + 1);

        // pack h -> SMEM, LN/logit partials
#pragma unroll
        for (int mt = 0; mt < 9; mt++)
#pragma unroll
            for (int rh = 0; rh < 2; rh++) {
                int r = mt * 16 + g + rh * 8;
                float v0 = acc[mt][0][rh * 2], v1 = acc[mt][0][rh * 2 + 1];
                float v2 = acc[mt][1][rh * 2], v3 = acc[mt][1][rh * 2 + 1];
                uint32_t p0 = packbf(v0, v1), p1 = packbf(v2, v3);
                *(uint32_t*)(sm + H_HI + hswz(r, cA)) = p0;
                *(uint32_t*)(sm + H_HI + hswz(r, cA + 8)) = p1;
                uint32_t l0 = packbf(v0 - __uint_as_float(p0 << 16),
                                     v1 - __uint_as_float(p0 & 0xffff0000u));
                uint32_t l1 = packbf(v2 - __uint_as_float(p1 << 16),
                                     v3 - __uint_as_float(p1 & 0xffff0000u));
                *(uint32_t*)(sm + H_LO + hswz(r, cA)) = l0;
                *(uint32_t*)(sm + H_LO + hswz(r, cA + 8)) = l1;

                float s1 = v0 + v1 + v2 + v3;
                float s2 = fmaf(v0, v0, fmaf(v1, v1, fmaf(v2, v2, v3 * v3)));
                float lp = fmaf(v0, awg4[0], fmaf(v1, awg4[1],
                           fmaf(v2, awg4[2], v3 * awg4[3])));
                s1 += __shfl_xor_sync(0xffffffffu, s1, 1);
                s1 += __shfl_xor_sync(0xffffffffu, s1, 2);
                s2 += __shfl_xor_sync(0xffffffffu, s2, 1);
                s2 += __shfl_xor_sync(0xffffffffu, s2, 2);
                lp += __shfl_xor_sync(0xffffffffu, lp, 1);
                lp += __shfl_xor_sync(0xffffffffu, lp, 2);
                if (q4 == 0) {
                    *(float2*)(sm + RED_O + (warp * 144 + r) * 8) = make_float2(s1, s2);
                    ((float*)(sm + LP_O))[warp * 144 + r] = lp;
                }
            }
        __syncthreads();

        // per-row finalize (threads 0..143)
        if (tid < 144) {
            float s1 = 0.f, s2 = 0.f, lp = 0.f;
#pragma unroll
            for (int w = 0; w < 8; w++) {
                float2 v = *(float2*)(sm + RED_O + (w * 144 + tid) * 8);
                s1 += v.x; s2 += v.y;
                lp += ((float*)(sm + LP_O))[w * 144 + tid];
            }
            float mu = s1 * (1.0f / 128.0f);
            float var = fmaf(s2, 1.0f / 128.0f, -mu * mu);
            float rstd = rsqrtf(var + 1e-5f);
            float l = fmaf(rstd, lp - mu * S1, S2);
            float mn = fmaxf(rs_m, l);
            float alpha = __expf(rs_m - mn);
            float beta  = __expf(l - mn);
            rs_m = mn;
            rs_s = fmaf(rs_s, alpha, beta);
            float br = beta * rstd;
            rs_q = fmaf(rs_q, alpha, br * mu);
            *(float2*)(sm + RAB_O + tid * 8) = make_float2(alpha, br);
        }
        __syncthreads();

        // P update
#pragma unroll
        for (int mt = 0; mt < 9; mt++)
#pragma unroll
            for (int rh = 0; rh < 2; rh++) {
                int r = mt * 16 + g + rh * 8;
                float2 ab = *(float2*)(sm + RAB_O + r * 8);
#pragma unroll
                for (int nt = 0; nt < 2; nt++) {
                    P[mt][nt][rh * 2]     = fmaf(P[mt][nt][rh * 2],     ab.x, ab.y * acc[mt][nt][rh * 2]);
                    P[mt][nt][rh * 2 + 1] = fmaf(P[mt][nt][rh * 2 + 1], ab.x, ab.y * acc[mt][nt][rh * 2 + 1]);
                }
            }
        // (h SMEM already updated; next mma reads after the wait+sync at loop top)
    }

    // ---- final: out = (Σ WG·P − q·WGsum)/s + WB + dense_b ----
    if (tid < CC) {
        int c2 = tid;
        float wg = 0.f, wb = 0.f;
        for (int k = 0; k < 128; k++) {
            float wd = dense_W[c2 * 128 + k];
            wg += wd * ln_g[k];
            wb += wd * ln_b[k];
        }
        ((float*)(sm + WGS_O))[c2] = wg;
        ((float*)(sm + WB_O))[c2] = wb;
    }
    {
        float g0 = ln_g[cA], g1 = ln_g[cA + 1], g2 = ln_g[cA + 8], g3 = ln_g[cA + 9];
        float wdg[CC][4];
#pragma unroll
        for (int c2 = 0; c2 < CC; c2++) {
            wdg[c2][0] = dense_W[c2 * 128 + cA] * g0;
            wdg[c2][1] = dense_W[c2 * 128 + cA + 1] * g1;
            wdg[c2][2] = dense_W[c2 * 128 + cA + 8] * g2;
            wdg[c2][3] = dense_W[c2 * 128 + cA + 9] * g3;
        }
        // OUTS overlay in UBUF: [8][144][10] fp32
#pragma unroll
        for (int mt = 0; mt < 9; mt++)
#pragma unroll
            for (int rh = 0; rh < 2; rh++) {
                int r = mt * 16 + g + rh * 8;
                float pv0 = P[mt][0][rh * 2], pv1 = P[mt][0][rh * 2 + 1];
                float pv2 = P[mt][1][rh * 2], pv3 = P[mt][1][rh * 2 + 1];
#pragma unroll
                for (int c2 = 0; c2 < CC; c2++) {
                    float s = fmaf(pv0, wdg[c2][0], fmaf(pv1, wdg[c2][1],
                              fmaf(pv2, wdg[c2][2], pv3 * wdg[c2][3])));
                    s += __shfl_xor_sync(0xffffffffu, s, 1);
                    s += __shfl_xor_sync(0xffffffffu, s, 2);
                    if (q4 == 0)
                        ((float*)(sm + UBUF))[(warp * 144 + r) * CC + c2] = s;
                }
            }
    }
    __syncthreads();
    if (tid < 144 && (n0 + tid) < NN) {
        float inv = 1.0f / rs_s;
#pragma unroll
        for (int c2 = 0; c2 < CC; c2++) {
            float tot = 0.f;
#pragma unroll
            for (int w = 0; w < 8; w++)
                tot += ((float*)(sm + UBUF))[(w * 144 + tid) * CC + c2];
            float val = (tot - rs_q * ((float*)(sm + WGS_O))[c2]) * inv
                        + ((float*)(sm + WB_O))[c2] + dense_b[c2];
            out[(n0 + tid) * CC + c2] = val;
        }
    }
}

// ===========================================================================
extern "C" void kernel_launch(void* const* d_in, const int* in_sizes, int n_in,
                              void* d_out, int out_size)
{
    const float* X       = (const float*)d_in[0];
    const float* W_ih    = (const float*)d_in[1];
    const float* W_hh    = (const float*)d_in[2];
    const float* b_ih    = (const float*)d_in[3];
    const float* b_hh    = (const float*)d_in[4];
    const float* ln_g    = (const float*)d_in[5];
    const float* ln_b    = (const float*)d_in[6];
    const float* attn_W  = (const float*)d_in[7];
    const float* attn_b  = (const float*)d_in[8];
    const float* dense_W = (const float*)d_in[9];
    const float* dense_b = (const float*)d_in[10];
    float* out = (float*)d_out;

    cudaFuncSetAttribute(u_gemm, cudaFuncAttributeMaxDynamicSharedMemorySize, K1_SMEM);
    cudaFuncSetAttribute(rnn_fused, cudaFuncAttributeMaxDynamicSharedMemorySize, K2_SMEM);

    u_gemm<<<(TT * NN) / 256, 256, K1_SMEM>>>(X, W_ih, b_ih, b_hh);
    rnn_fused<<<(NN + 143) / 144, 256, K2_SMEM>>>(W_hh, ln_g, ln_b, attn_W, attn_b,
                                                  dense_W, dense_b, out);
}

// round 5
// speedup vs baseline: 5.0528x; 1.2030x over previous
#include <cuda_runtime.h>
#include <cuda_bf16.h>
#include <cstdint>

#define TT 32
#define NN 20000
#define CC 10

// ---------------- SMEM layout (bytes) ----------------
#define WHH_HI 0          /* bf16 [128][128] swizzled */
#define WHH_LO 32768
#define H_HI   65536      /* bf16 [144][128] swizzled */
#define H_LO   102400
#define X_HI   139264     /* stages Wih_hi at init; then x_hi; then OUTS overlay */
#define X_LO   176128     /* stages Wih_lo at init; then x_lo */
#define RED_O  212992     /* float2 [8][144] (s1,s2) */
#define LP_O   222208     /* float  [8][144] */
#define RAB_O  226816     /* float2 [144] (alpha, beta*rstd) */
#define SCAL_O 227968     /* float[2]: S1, S2 */
#define WGS_O  227976     /* float[10] */
#define WB_O   228016     /* float[10] */
#define SMEMSZ 228064

// ---------------------------------------------------------------------------
__device__ __forceinline__ uint32_t smem_u32_of(const void* p) {
    uint32_t a;
    asm("{ .reg .u64 t; cvta.to.shared.u64 t, %1; cvt.u32.u64 %0, t; }" : "=r"(a) : "l"(p));
    return a;
}
__device__ __forceinline__ void mma_bf16(float* c, const uint32_t* a, const uint32_t* b) {
    asm volatile("mma.sync.aligned.m16n8k16.row.col.f32.bf16.bf16.f32 "
        "{%0,%1,%2,%3}, {%4,%5,%6,%7}, {%8,%9}, {%0,%1,%2,%3};"
        : "+f"(c[0]), "+f"(c[1]), "+f"(c[2]), "+f"(c[3])
        : "r"(a[0]), "r"(a[1]), "r"(a[2]), "r"(a[3]), "r"(b[0]), "r"(b[1]));
}
__device__ __forceinline__ void ldsm4(uint32_t* r, uint32_t addr) {
    asm volatile("ldmatrix.sync.aligned.m8n8.x4.shared.b16 {%0,%1,%2,%3}, [%4];"
        : "=r"(r[0]), "=r"(r[1]), "=r"(r[2]), "=r"(r[3]) : "r"(addr));
}
__device__ __forceinline__ void ldsm2(uint32_t* r, uint32_t addr) {
    asm volatile("ldmatrix.sync.aligned.m8n8.x2.shared.b16 {%0,%1}, [%2];"
        : "=r"(r[0]), "=r"(r[1]) : "r"(addr));
}
// swizzled byte offset in a [rows][128] bf16 tile (256 B/row)
__device__ __forceinline__ uint32_t hswz(int r, int k) {
    int k8 = k >> 3;
    int s = (k8 & 8) | ((k8 ^ r) & 7);
    return (uint32_t)(r * 256 + s * 16 + (k & 7) * 2);
}
__device__ __forceinline__ uint32_t packbf(float a, float b) {
    uint32_t p;
    asm("cvt.rn.bf16x2.f32 %0, %1, %2;" : "=r"(p) : "f"(b), "f"(a));
    return p;
}
__device__ __forceinline__ void conv_weight(const float* __restrict__ W,
                                            char* hi, char* lo, int tid) {
    for (int idx = tid; idx < 16384; idx += 256) {
        int r = idx >> 7, k = idx & 127;
        float w = W[idx];
        __nv_bfloat16 wh = __float2bfloat16(w);
        uint32_t o = hswz(r, k);
        *(__nv_bfloat16*)(hi + o) = wh;
        *(__nv_bfloat16*)(lo + o) = __float2bfloat16(w - __bfloat162float(wh));
    }
}

// ===========================================================================
// Single fused kernel: 144 rows/CTA, grid 139 (one wave), 8 warps, each warp
// owns 16 output cols. Wih hi/lo as register fragments; Whh tiles in SMEM.
// Per step: acc = X[t]@Wih^T + h@Whh^T (6 split-bf16 products) -> relu+bias
// -> h ; LN + online-softmax attention + P accumulation ; X[t+1] refill.
// ===========================================================================
__global__ __launch_bounds__(256, 1) void grn_one(
    const float* __restrict__ X,
    const float* __restrict__ W_ih,  const float* __restrict__ W_hh,
    const float* __restrict__ b_ih,  const float* __restrict__ b_hh,
    const float* __restrict__ ln_g,  const float* __restrict__ ln_b,
    const float* __restrict__ attn_W, const float* __restrict__ attn_b,
    const float* __restrict__ dense_W, const float* __restrict__ dense_b,
    float* __restrict__ out)
{
    extern __shared__ char sm[];
    const uint32_t sb = smem_u32_of(sm);
    const int tid = threadIdx.x, warp = tid >> 5, lane = tid & 31;
    const int g = lane >> 2, q4 = lane & 3;
    const int nw = warp * 16;
    const int n0 = blockIdx.x * 144;
    const int cA = nw + q4 * 2;
    const int ar = lane & 15;
    const int akbase = ((lane >> 4) << 3);
    const int bn = nw + (lane & 7);
    const int bkoff = (((lane >> 3) & 1) << 3);

    // ---- stage weights: Wih -> X region (temp), Whh -> its tiles ----
    conv_weight(W_ih, sm + X_HI, sm + X_LO, tid);
    conv_weight(W_hh, sm + WHH_HI, sm + WHH_LO, tid);
    if (tid == 0) {
        float s1 = 0.f, s2 = 0.f;
        for (int c = 0; c < 128; c++) {
            s1 += attn_W[c] * ln_g[c];
            s2 += attn_W[c] * ln_b[c];
        }
        ((float*)(sm + SCAL_O))[0] = s1;
        ((float*)(sm + SCAL_O))[1] = s2 + attn_b[0];
    }
    __syncthreads();

    // ---- Wih fragments -> registers (per-warp, its 16 cols, all K) ----
    uint32_t wihH[8][4], wihL[8][4];
#pragma unroll
    for (int k0 = 0; k0 < 8; k0++) {
        int bk = k0 * 16 + bkoff;
        ldsm2(&wihH[k0][0], sb + X_HI + hswz(bn, bk));
        ldsm2(&wihH[k0][2], sb + X_HI + hswz(bn + 8, bk));
        ldsm2(&wihL[k0][0], sb + X_LO + hswz(bn, bk));
        ldsm2(&wihL[k0][2], sb + X_LO + hswz(bn + 8, bk));
    }
    __syncthreads();   // staging consumed; X region now free for X tiles

    // per-thread constants
    float b4[4], awg4[4];
    b4[0] = b_ih[cA] + b_hh[cA];       b4[1] = b_ih[cA + 1] + b_hh[cA + 1];
    b4[2] = b_ih[cA + 8] + b_hh[cA + 8]; b4[3] = b_ih[cA + 9] + b_hh[cA + 9];
    awg4[0] = attn_W[cA] * ln_g[cA];       awg4[1] = attn_W[cA + 1] * ln_g[cA + 1];
    awg4[2] = attn_W[cA + 8] * ln_g[cA + 8]; awg4[3] = attn_W[cA + 9] * ln_g[cA + 9];
    const float S1 = ((float*)(sm + SCAL_O))[0];
    const float S2 = ((float*)(sm + SCAL_O))[1];

    // ---- X loader: global fp32 -> split-bf16 swizzled x tiles ----
    auto loadX = [&](int t) {
#pragma unroll
        for (int j = 0; j < 18; j++) {
            int fi = tid + j * 256;          // 0..4607 float4 chunks
            int lr = fi >> 5, c4 = fi & 31;
            int gr = n0 + lr; if (gr > NN - 1) gr = NN - 1;
            float4 x = *(const float4*)(X + ((size_t)t * NN + gr) * 128 + c4 * 4);
            uint32_t h0 = packbf(x.x, x.y), h1 = packbf(x.z, x.w);
            float r0 = x.x - __uint_as_float(h0 << 16);
            float r1 = x.y - __uint_as_float(h0 & 0xffff0000u);
            float r2 = x.z - __uint_as_float(h1 << 16);
            float r3 = x.w - __uint_as_float(h1 & 0xffff0000u);
            uint32_t l0 = packbf(r0, r1), l1 = packbf(r2, r3);
            *(uint2*)(sm + X_HI + hswz(lr, c4 * 4)) = make_uint2(h0, h1);
            *(uint2*)(sm + X_LO + hswz(lr, c4 * 4)) = make_uint2(l0, l1);
        }
    };
    loadX(0);
    __syncthreads();

    float acc[9][2][4];
#pragma unroll
    for (int mt = 0; mt < 9; mt++)
#pragma unroll
        for (int nt = 0; nt < 2; nt++)
#pragma unroll
            for (int i = 0; i < 4; i++) acc[mt][nt][i] = 0.f;

    // ---- h0 = X[0]@Wih^T + bias (no relu): x-only mma ----
#pragma unroll
    for (int k0 = 0; k0 < 8; k0++) {
        const int akb = akbase + k0 * 16;
#pragma unroll
        for (int mt = 0; mt < 9; mt++) {
            uint32_t xh[4], xl[4];
            ldsm4(xh, sb + X_HI + hswz(mt * 16 + ar, akb));
            ldsm4(xl, sb + X_LO + hswz(mt * 16 + ar, akb));
            mma_bf16(acc[mt][0], xh, &wihH[k0][0]);
            mma_bf16(acc[mt][1], xh, &wihH[k0][2]);
            mma_bf16(acc[mt][0], xh, &wihL[k0][0]);
            mma_bf16(acc[mt][1], xh, &wihL[k0][2]);
            mma_bf16(acc[mt][0], xl, &wihH[k0][0]);
            mma_bf16(acc[mt][1], xl, &wihH[k0][2]);
        }
    }
    // pack h0 (keep x tiles intact: step t=0 reuses X[0])
#pragma unroll
    for (int mt = 0; mt < 9; mt++)
#pragma unroll
        for (int rh = 0; rh < 2; rh++) {
            int r = mt * 16 + g + rh * 8;
            float v0 = acc[mt][0][rh * 2] + b4[0], v1 = acc[mt][0][rh * 2 + 1] + b4[1];
            float v2 = acc[mt][1][rh * 2] + b4[2], v3 = acc[mt][1][rh * 2 + 1] + b4[3];
            uint32_t p0 = packbf(v0, v1), p1 = packbf(v2, v3);
            *(uint32_t*)(sm + H_HI + hswz(r, cA)) = p0;
            *(uint32_t*)(sm + H_HI + hswz(r, cA + 8)) = p1;
            uint32_t l0 = packbf(v0 - __uint_as_float(p0 << 16),
                                 v1 - __uint_as_float(p0 & 0xffff0000u));
            uint32_t l1 = packbf(v2 - __uint_as_float(p1 << 16),
                                 v3 - __uint_as_float(p1 & 0xffff0000u));
            *(uint32_t*)(sm + H_LO + hswz(r, cA)) = l0;
            *(uint32_t*)(sm + H_LO + hswz(r, cA + 8)) = l1;
        }
    __syncthreads();

    float P[9][2][4];
#pragma unroll
    for (int mt = 0; mt < 9; mt++)
#pragma unroll
        for (int nt = 0; nt < 2; nt++)
#pragma unroll
            for (int i = 0; i < 4; i++) P[mt][nt][i] = 0.f;
    float rs_m = -INFINITY, rs_s = 0.f, rs_q = 0.f;

    // =================== time loop ===================
    for (int t = 0; t < TT; t++) {
#pragma unroll
        for (int mt = 0; mt < 9; mt++)
#pragma unroll
            for (int nt = 0; nt < 2; nt++)
#pragma unroll
                for (int i = 0; i < 4; i++) acc[mt][nt][i] = 0.f;

        // combined mma: acc = h@Whh^T + X[t]@Wih^T (3+3 products)
#pragma unroll
        for (int k0 = 0; k0 < 8; k0++) {
            int bk = k0 * 16 + bkoff;
            uint32_t bh0[2], bh1[2], bl0[2], bl1[2];
            ldsm2(bh0, sb + WHH_HI + hswz(bn, bk));
            ldsm2(bh1, sb + WHH_HI + hswz(bn + 8, bk));
            ldsm2(bl0, sb + WHH_LO + hswz(bn, bk));
            ldsm2(bl1, sb + WHH_LO + hswz(bn + 8, bk));
            const int akb = akbase + k0 * 16;
#pragma unroll
            for (int mt = 0; mt < 9; mt++) {
                uint32_t hh[4], hl[4], xh[4], xl[4];
                ldsm4(hh, sb + H_HI + hswz(mt * 16 + ar, akb));
                ldsm4(hl, sb + H_LO + hswz(mt * 16 + ar, akb));
                ldsm4(xh, sb + X_HI + hswz(mt * 16 + ar, akb));
                ldsm4(xl, sb + X_LO + hswz(mt * 16 + ar, akb));
                mma_bf16(acc[mt][0], hh, bh0);
                mma_bf16(acc[mt][1], hh, bh1);
                mma_bf16(acc[mt][0], hh, bl0);
                mma_bf16(acc[mt][1], hh, bl1);
                mma_bf16(acc[mt][0], hl, bh0);
                mma_bf16(acc[mt][1], hl, bh1);
                mma_bf16(acc[mt][0], xh, &wihH[k0][0]);
                mma_bf16(acc[mt][1], xh, &wihH[k0][2]);
                mma_bf16(acc[mt][0], xh, &wihL[k0][0]);
                mma_bf16(acc[mt][1], xh, &wihL[k0][2]);
                mma_bf16(acc[mt][0], xl, &wihH[k0][0]);
                mma_bf16(acc[mt][1], xl, &wihH[k0][2]);
            }
        }
        __syncthreads();   // h & x tiles free

        // h_{t+1} = relu(acc + bias); pack; LN/logit partials
#pragma unroll
        for (int mt = 0; mt < 9; mt++)
#pragma unroll
            for (int rh = 0; rh < 2; rh++) {
                int r = mt * 16 + g + rh * 8;
                float v0 = fmaxf(acc[mt][0][rh * 2]     + b4[0], 0.f);
                float v1 = fmaxf(acc[mt][0][rh * 2 + 1] + b4[1], 0.f);
                float v2 = fmaxf(acc[mt][1][rh * 2]     + b4[2], 0.f);
                float v3 = fmaxf(acc[mt][1][rh * 2 + 1] + b4[3], 0.f);
                acc[mt][0][rh * 2] = v0; acc[mt][0][rh * 2 + 1] = v1;
                acc[mt][1][rh * 2] = v2; acc[mt][1][rh * 2 + 1] = v3;
                uint32_t p0 = packbf(v0, v1), p1 = packbf(v2, v3);
                *(uint32_t*)(sm + H_HI + hswz(r, cA)) = p0;
                *(uint32_t*)(sm + H_HI + hswz(r, cA + 8)) = p1;
                uint32_t l0 = packbf(v0 - __uint_as_float(p0 << 16),
                                     v1 - __uint_as_float(p0 & 0xffff0000u));
                uint32_t l1 = packbf(v2 - __uint_as_float(p1 << 16),
                                     v3 - __uint_as_float(p1 & 0xffff0000u));
                *(uint32_t*)(sm + H_LO + hswz(r, cA)) = l0;
                *(uint32_t*)(sm + H_LO + hswz(r, cA + 8)) = l1;

                float s1 = v0 + v1 + v2 + v3;
                float s2 = fmaf(v0, v0, fmaf(v1, v1, fmaf(v2, v2, v3 * v3)));
                float lp = fmaf(v0, awg4[0], fmaf(v1, awg4[1],
                           fmaf(v2, awg4[2], v3 * awg4[3])));
                s1 += __shfl_xor_sync(0xffffffffu, s1, 1);
                s1 += __shfl_xor_sync(0xffffffffu, s1, 2);
                s2 += __shfl_xor_sync(0xffffffffu, s2, 1);
                s2 += __shfl_xor_sync(0xffffffffu, s2, 2);
                lp += __shfl_xor_sync(0xffffffffu, lp, 1);
                lp += __shfl_xor_sync(0xffffffffu, lp, 2);
                if (q4 == 0) {
                    *(float2*)(sm + RED_O + (warp * 144 + r) * 8) = make_float2(s1, s2);
                    ((float*)(sm + LP_O))[warp * 144 + r] = lp;
                }
            }
        __syncthreads();

        // per-row finalize -> (alpha, beta*rstd)
        if (tid < 144) {
            float s1 = 0.f, s2 = 0.f, lp = 0.f;
#pragma unroll
            for (int w = 0; w < 8; w++) {
                float2 v = *(float2*)(sm + RED_O + (w * 144 + tid) * 8);
                s1 += v.x; s2 += v.y;
                lp += ((float*)(sm + LP_O))[w * 144 + tid];
            }
            float mu = s1 * (1.0f / 128.0f);
            float var = fmaf(s2, 1.0f / 128.0f, -mu * mu);
            float rstd = rsqrtf(var + 1e-5f);
            float l = fmaf(rstd, lp - mu * S1, S2);
            float mn = fmaxf(rs_m, l);
            float alpha = __expf(rs_m - mn);
            float beta  = __expf(l - mn);
            rs_m = mn;
            rs_s = fmaf(rs_s, alpha, beta);
            float br = beta * rstd;
            rs_q = fmaf(rs_q, alpha, br * mu);
            *(float2*)(sm + RAB_O + tid * 8) = make_float2(alpha, br);
        }
        __syncthreads();

        // P update (acc holds h_{t+1} values)
#pragma unroll
        for (int mt = 0; mt < 9; mt++)
#pragma unroll
            for (int rh = 0; rh < 2; rh++) {
                int r = mt * 16 + g + rh * 8;
                float2 ab = *(float2*)(sm + RAB_O + r * 8);
#pragma unroll
                for (int nt = 0; nt < 2; nt++) {
                    P[mt][nt][rh * 2]     = fmaf(P[mt][nt][rh * 2],     ab.x, ab.y * acc[mt][nt][rh * 2]);
                    P[mt][nt][rh * 2 + 1] = fmaf(P[mt][nt][rh * 2 + 1], ab.x, ab.y * acc[mt][nt][rh * 2 + 1]);
                }
            }

        if (t < TT - 1) loadX(t + 1);
        __syncthreads();   // x tiles ready; RAB consumed
    }

    // ---- final: out = (Σ Wd·γ·P − q·Σ(Wd·γ))/s + Σ(Wd·β) + dense_b ----
    if (tid < CC) {
        float wg = 0.f, wb = 0.f;
        for (int k = 0; k < 128; k++) {
            float wd = dense_W[tid * 128 + k];
            wg += wd * ln_g[k];
            wb += wd * ln_b[k];
        }
        ((float*)(sm + WGS_O))[tid] = wg;
        ((float*)(sm + WB_O))[tid] = wb;
    }
    {
        float g0 = ln_g[cA], g1 = ln_g[cA + 1], g2 = ln_g[cA + 8], g3 = ln_g[cA + 9];
        float wdg[CC][4];
#pragma unroll
        for (int c2 = 0; c2 < CC; c2++) {
            wdg[c2][0] = dense_W[c2 * 128 + cA] * g0;
            wdg[c2][1] = dense_W[c2 * 128 + cA + 1] * g1;
            wdg[c2][2] = dense_W[c2 * 128 + cA + 8] * g2;
            wdg[c2][3] = dense_W[c2 * 128 + cA + 9] * g3;
        }
        // OUTS overlay in X region: [8][144][10] fp32
#pragma unroll
        for (int mt = 0; mt < 9; mt++)
#pragma unroll
            for (int rh = 0; rh < 2; rh++) {
                int r = mt * 16 + g + rh * 8;
                float pv0 = P[mt][0][rh * 2], pv1 = P[mt][0][rh * 2 + 1];
                float pv2 = P[mt][1][rh * 2], pv3 = P[mt][1][rh * 2 + 1];
#pragma unroll
                for (int c2 = 0; c2 < CC; c2++) {
                    float s = fmaf(pv0, wdg[c2][0], fmaf(pv1, wdg[c2][1],
                              fmaf(pv2, wdg[c2][2], pv3 * wdg[c2][3])));
                    s += __shfl_xor_sync(0xffffffffu, s, 1);
                    s += __shfl_xor_sync(0xffffffffu, s, 2);
                    if (q4 == 0)
                        ((float*)(sm + X_HI))[(warp * 144 + r) * CC + c2] = s;
                }
            }
    }
    __syncthreads();
    if (tid < 144 && (n0 + tid) < NN) {
        float inv = 1.0f / rs_s;
#pragma unroll
        for (int c2 = 0; c2 < CC; c2++) {
            float tot = 0.f;
#pragma unroll
            for (int w = 0; w < 8; w++)
                tot += ((float*)(sm + X_HI))[(w * 144 + tid) * CC + c2];
            float val = (tot - rs_q * ((float*)(sm + WGS_O))[c2]) * inv
                        + ((float*)(sm + WB_O))[c2] + dense_b[c2];
            out[(n0 + tid) * CC + c2] = val;
        }
    }
}

// ===========================================================================
extern "C" void kernel_launch(void* const* d_in, const int* in_sizes, int n_in,
                              void* d_out, int out_size)
{
    const float* X       = (const float*)d_in[0];
    const float* W_ih    = (const float*)d_in[1];
    const float* W_hh    = (const float*)d_in[2];
    const float* b_ih    = (const float*)d_in[3];
    const float* b_hh    = (const float*)d_in[4];
    const float* ln_g    = (const float*)d_in[5];
    const float* ln_b    = (const float*)d_in[6];
    const float* attn_W  = (const float*)d_in[7];
    const float* attn_b  = (const float*)d_in[8];
    const float* dense_W = (const float*)d_in[9];
    const float* dense_b = (const float*)d_in[10];
    float* out = (float*)d_out;

    cudaFuncSetAttribute(grn_one, cudaFuncAttributeMaxDynamicSharedMemorySize, SMEMSZ);

    grn_one<<<(NN + 143) / 144, 256, SMEMSZ>>>(
        X, W_ih, W_hh, b_ih, b_hh, ln_g, ln_b, attn_W, attn_b,
        dense_W, dense_b, out);
}